// round 1
// baseline (speedup 1.0000x reference)
#include <cuda_runtime.h>

#define NMAX 200000
#define EMAX 400000
#define DD 128
#define HH 4

// ---------------- scratch (device globals; no allocation) ----------------
__device__ __align__(16) float g_h[NMAX*DD];
__device__ __align__(16) float g_xl[NMAX*DD];
__device__ __align__(16) float g_xr[NMAX*DD];
__device__ __align__(16) float g_num[NMAX*DD];
__device__ __align__(16) float g_efull[(EMAX+NMAX)*HH];
__device__ __align__(16) float g_sums[NMAX*HH];
__device__ float    g_logits[(EMAX+NMAX)*HH];
__device__ unsigned g_mkey[NMAX*HH];
__device__ float    g_z[NMAX*HH];
__device__ float    g_cnt[NMAX];

// order-preserving float<->uint key for atomicMax on floats
__device__ __forceinline__ unsigned fkey(float f){
    unsigned u = __float_as_uint(f);
    return (u & 0x80000000u) ? ~u : (u | 0x80000000u);
}
__device__ __forceinline__ float keyf(unsigned k){
    unsigned u = (k & 0x80000000u) ? (k & 0x7fffffffu) : ~k;
    return __uint_as_float(u);
}

// vector float4 reduction (sm_90+)
__device__ __forceinline__ void red4(float* p, float a, float b, float c, float d){
    asm volatile("red.global.add.v4.f32 [%0], {%1,%2,%3,%4};"
                 :: "l"(p), "f"(a), "f"(b), "f"(c), "f"(d) : "memory");
}

// ---------------- atom encoder: h[i,d] = sum_f tables[f, x[i,f], d] ----------------
__global__ void k_atom(const float* __restrict__ tab, const int* __restrict__ x, int n){
    int i = blockIdx.x;
    int d = threadIdx.x;
    __shared__ int xf[9];
    if (d < 9) xf[d] = x[i*9 + d];
    __syncthreads();
    float s = 0.f;
#pragma unroll
    for (int f = 0; f < 9; ++f)
        s += tab[(f*16 + xf[f])*DD + d];
    g_h[i*DD + d] = s;
}

__global__ void k_zero_node(int n){
    int i = blockIdx.x*blockDim.x + threadIdx.x;
    if (i >= n) return;
    g_cnt[i] = 0.f;
    *(float4*)(g_sums + i*4) = make_float4(0.f,0.f,0.f,0.f);
}

// bond embeddings + per-dst sums/counts for self-loop mean
__global__ void k_edge(const float* __restrict__ bond, const int* __restrict__ ei,
                       const int* __restrict__ ea, int E_){
    int e = blockIdx.x*blockDim.x + threadIdx.x;
    if (e >= E_) return;
    int tt  = ea[e];
    int dst = ei[E_ + e];
    float4 b = *(const float4*)(bond + tt*4);
    *(float4*)(g_efull + e*4) = b;
    red4(g_sums + dst*4, b.x, b.y, b.z, b.w);
    atomicAdd(g_cnt + dst, 1.0f);
}

__global__ void k_self(int E_, int n){
    int i = blockIdx.x*blockDim.x + threadIdx.x;
    if (i >= n) return;
    float inv = 1.0f / fmaxf(g_cnt[i], 1.0f);
    float4 s = *(const float4*)(g_sums + i*4);
    *(float4*)(g_efull + (E_ + i)*4) = make_float4(s.x*inv, s.y*inv, s.z*inv, s.w*inv);
}

__global__ void k_zero_layer(int n){
    int i = blockIdx.x*blockDim.x + threadIdx.x;
    if (i < n*32) *(float4*)(g_num + i*4) = make_float4(0.f,0.f,0.f,0.f);
    if (i < n*4){ g_z[i] = 0.f; g_mkey[i] = 0u; }
}

// ---------------- dual GEMM: xl = h@Wl + bl ; xr = h@Wr + br ----------------
// 256 threads: t<128 -> xl column t, t>=128 -> xr column t-128.
// Both W matrices (128KB) live in smem; 8 nodes register-blocked per iter.
__global__ void k_gemm(const float* __restrict__ Wl, const float* __restrict__ bl,
                       const float* __restrict__ Wr, const float* __restrict__ br, int n){
    extern __shared__ float smem[];
    float* sW = smem;            // [128][256]
    float* sh = smem + DD*256;   // [8][128]
    int t = threadIdx.x;
    for (int idx = t; idx < DD*DD; idx += 256){
        int k = idx >> 7, c = idx & 127;
        sW[k*256 + c]       = Wl[idx];
        sW[k*256 + 128 + c] = Wr[idx];
    }
    float bias = (t < 128) ? bl[t] : br[t - 128];
    __syncthreads();

    for (int base = blockIdx.x*8; base < n; base += gridDim.x*8){
        int nn = min(8, n - base);
        __syncthreads();
        for (int i = t; i < 8*DD; i += 256)
            sh[i] = (i < nn*DD) ? g_h[base*DD + i] : 0.0f;
        __syncthreads();
        float acc[8];
#pragma unroll
        for (int j = 0; j < 8; ++j) acc[j] = bias;
#pragma unroll 8
        for (int k = 0; k < DD; ++k){
            float w = sW[k*256 + t];
#pragma unroll
            for (int j = 0; j < 8; ++j)
                acc[j] += sh[j*DD + k] * w;
        }
        float* dst = (t < 128) ? (g_xl + base*DD + t) : (g_xr + base*DD + (t - 128));
#pragma unroll
        for (int j = 0; j < 8; ++j)
            if (j < nn) dst[j*DD] = acc[j];
    }
}

// ---------------- pass A: per-edge logits + per-(dst,head) max ----------------
// warp per edge; lane handles 4 consecutive channels; heads = lane/8.
__global__ void k_passA(const int* __restrict__ ei, const float* __restrict__ We,
                        const float* __restrict__ att, int E_, int n){
    __shared__ float sWe[4*DD];
    __shared__ float sAtt[DD];
    int t = threadIdx.x;
    for (int i = t; i < 4*DD; i += 256) sWe[i] = We[i];
    if (t < DD) sAtt[t] = att[t];
    __syncthreads();

    int gw   = blockIdx.x*8 + (t >> 5);
    int lane = t & 31;
    int M = E_ + n;
    if (gw >= M) return;
    int src, dst;
    if (gw < E_){ src = ei[gw]; dst = ei[E_ + gw]; } else { src = dst = gw - E_; }

    int c0 = lane*4;
    float4 a4 = *(const float4*)(g_xl + src*DD + c0);
    float4 b4 = *(const float4*)(g_xr + dst*DD + c0);
    float4 e4 = *(const float4*)(g_efull + gw*4);
    float av[4] = {a4.x, a4.y, a4.z, a4.w};
    float bv[4] = {b4.x, b4.y, b4.z, b4.w};
    float p = 0.f;
#pragma unroll
    for (int j = 0; j < 4; ++j){
        int c = c0 + j;
        float ee = e4.x*sWe[c] + e4.y*sWe[DD + c] + e4.z*sWe[2*DD + c] + e4.w*sWe[3*DD + c];
        float g = av[j] + bv[j] + ee;
        g = (g > 0.f) ? g : 0.2f*g;
        p += g * sAtt[c];
    }
    p += __shfl_xor_sync(0xffffffffu, p, 1);
    p += __shfl_xor_sync(0xffffffffu, p, 2);
    p += __shfl_xor_sync(0xffffffffu, p, 4);
    if ((lane & 7) == 0){
        int h = lane >> 3;
        g_logits[gw*4 + h] = p;
        atomicMax(g_mkey + dst*4 + h, fkey(p));
    }
}

// ---------------- pass B: w = exp(logit - m); accumulate z and numerator ----------------
__global__ void k_passB(const int* __restrict__ ei, int E_, int n){
    int t = threadIdx.x;
    int gw   = blockIdx.x*8 + (t >> 5);
    int lane = t & 31;
    int M = E_ + n;
    if (gw >= M) return;
    int src, dst;
    if (gw < E_){ src = ei[gw]; dst = ei[E_ + gw]; } else { src = dst = gw - E_; }

    int h = lane >> 3;
    float w = 0.f;
    if ((lane & 7) == 0){
        float lg = g_logits[gw*4 + h];
        float m  = keyf(g_mkey[dst*4 + h]);
        w = expf(lg - m);
        atomicAdd(g_z + dst*4 + h, w);
    }
    w = __shfl_sync(0xffffffffu, w, lane & 24);  // broadcast from head leader
    float4 a4 = *(const float4*)(g_xl + src*DD + lane*4);
    red4(g_num + dst*DD + lane*4, a4.x*w, a4.y*w, a4.z*w, a4.w*w);
}

// ---------------- finalize: h = num / (z + 1e-16) + cb ; relu ----------------
__global__ void k_fin(const float* __restrict__ cb, int n, int dorelu){
    int idx = blockIdx.x*blockDim.x + threadIdx.x;
    if (idx >= n*DD) return;
    int i = idx >> 7, c = idx & 127;
    float v = g_num[idx] / (g_z[(i << 2) + (c >> 5)] + 1e-16f) + cb[c];
    if (dorelu) v = fmaxf(v, 0.0f);
    g_h[idx] = v;
}

// ---------------- head ----------------
__global__ void k_head(float* out, const float* __restrict__ bout, int G){
    int g = blockIdx.x*blockDim.x + threadIdx.x;
    if (g < G) out[g] = bout[0];
}

__global__ void k_pool(const float* __restrict__ Wout, const int* __restrict__ bid,
                       float* out, int n){
    int gw   = blockIdx.x*8 + (threadIdx.x >> 5);
    int lane = threadIdx.x & 31;
    if (gw >= n) return;
    float4 hv = *(const float4*)(g_h + gw*DD + lane*4);
    float4 wv = *(const float4*)(Wout + lane*4);
    float p = hv.x*wv.x + hv.y*wv.y + hv.z*wv.z + hv.w*wv.w;
#pragma unroll
    for (int o = 16; o > 0; o >>= 1) p += __shfl_xor_sync(0xffffffffu, p, o);
    if (lane == 0) atomicAdd(out + bid[gw], p);
}

// ---------------- launch ----------------
extern "C" void kernel_launch(void* const* d_in, const int* in_sizes, int n_in,
                              void* d_out, int out_size){
    const float* atab = (const float*)d_in[0];
    const float* bond = (const float*)d_in[1];
    const float* Wl   = (const float*)d_in[2];
    const float* bl   = (const float*)d_in[3];
    const float* Wr   = (const float*)d_in[4];
    const float* br   = (const float*)d_in[5];
    const float* We   = (const float*)d_in[6];
    const float* att  = (const float*)d_in[7];
    const float* cb   = (const float*)d_in[8];
    const float* Wout = (const float*)d_in[9];
    const float* bout = (const float*)d_in[10];
    const int*   x    = (const int*)d_in[11];
    const int*   ei   = (const int*)d_in[12];
    const int*   ea   = (const int*)d_in[13];
    const int*   bid  = (const int*)d_in[14];

    int n  = in_sizes[11] / 9;
    int E_ = in_sizes[13];
    int G  = out_size;
    float* out = (float*)d_out;

    const int SMEM = DD*256*4 + 8*DD*4;  // 132 KB
    cudaFuncSetAttribute(k_gemm, cudaFuncAttributeMaxDynamicSharedMemorySize, SMEM);

    int nb = (n + 255)/256;
    int M  = E_ + n;
    int mb = (M + 7)/8;

    k_atom<<<n, 128>>>(atab, x, n);
    k_zero_node<<<nb, 256>>>(n);
    k_edge<<<(E_ + 255)/256, 256>>>(bond, ei, ea, E_);
    k_self<<<nb, 256>>>(E_, n);

    for (int l = 0; l < 4; ++l){
        k_zero_layer<<<(n*32 + 255)/256, 256>>>(n);
        k_gemm<<<148, 256, SMEM>>>(Wl + l*DD*DD, bl + l*DD, Wr + l*DD*DD, br + l*DD, n);
        k_passA<<<mb, 256>>>(ei, We + l*4*DD, att + l*DD, E_, n);
        k_passB<<<mb, 256>>>(ei, E_, n);
        k_fin<<<(n*DD + 255)/256, 256>>>(cb + l*DD, n, (l < 3) ? 1 : 0);
    }

    k_head<<<(G + 255)/256, 256>>>(out, bout, G);
    k_pool<<<(n + 7)/8, 256>>>(Wout, bid, out, n);
}

// round 2
// speedup vs baseline: 2.1057x; 2.1057x over previous
#include <cuda_runtime.h>

#define NMAX 200000
#define EMAX 400000
#define DD 128
#define HH 4
#define GDIM 148

// ---------------- scratch (device globals; no allocation) ----------------
__device__ __align__(16) float g_h[NMAX*DD];
__device__ __align__(16) float g_xl[NMAX*DD];
__device__ __align__(16) float g_xr[NMAX*DD];
__device__ __align__(16) float g_num[NMAX*DD];
__device__ __align__(16) float g_efull[(EMAX+NMAX)*HH];
__device__ __align__(16) float g_sums[NMAX*HH];
__device__ float g_z[2][NMAX*HH];       // double-buffered softmax denominators
__device__ float g_cnt[NMAX];

// vector float4 reduction (sm_90+)
__device__ __forceinline__ void red4(float* p, float a, float b, float c, float d){
    asm volatile("red.global.add.v4.f32 [%0], {%1,%2,%3,%4};"
                 :: "l"(p), "f"(a), "f"(b), "f"(c), "f"(d) : "memory");
}

// ---------------- atom encoder: h[i,d] = sum_f tables[f, x[i,f], d] ----------------
__global__ void k_atom(const float* __restrict__ tab, const int* __restrict__ x, int n){
    int i = blockIdx.x;
    int d = threadIdx.x;
    __shared__ int xf[9];
    if (d < 9) xf[d] = x[i*9 + d];
    __syncthreads();
    float s = 0.f;
#pragma unroll
    for (int f = 0; f < 9; ++f)
        s += tab[(f*16 + xf[f])*DD + d];
    g_h[i*DD + d] = s;
}

// zero all per-layer accumulators once at start
__global__ void k_init(int n){
    long long idx = (long long)blockIdx.x*blockDim.x + threadIdx.x;
    long long tot = (long long)n*DD;
    for (long long i = idx; i < tot; i += (long long)gridDim.x*blockDim.x)
        g_num[i] = 0.f;
    if (idx < n){
        g_cnt[idx] = 0.f;
        *(float4*)(g_sums + idx*4) = make_float4(0.f,0.f,0.f,0.f);
        *(float4*)(&g_z[0][idx*4]) = make_float4(0.f,0.f,0.f,0.f);
        *(float4*)(&g_z[1][idx*4]) = make_float4(0.f,0.f,0.f,0.f);
    }
}

// bond embeddings + per-dst sums/counts for self-loop mean
__global__ void k_edge(const float* __restrict__ bond, const int* __restrict__ ei,
                       const int* __restrict__ ea, int E_){
    int e = blockIdx.x*blockDim.x + threadIdx.x;
    if (e >= E_) return;
    int tt  = ea[e];
    int dst = ei[E_ + e];
    float4 b = *(const float4*)(bond + tt*4);
    *(float4*)(g_efull + e*4) = b;
    red4(g_sums + dst*4, b.x, b.y, b.z, b.w);
    atomicAdd(g_cnt + dst, 1.0f);
}

__global__ void k_self(int E_, int n){
    int i = blockIdx.x*blockDim.x + threadIdx.x;
    if (i >= n) return;
    float inv = 1.0f / fmaxf(g_cnt[i], 1.0f);
    float4 s = *(const float4*)(g_sums + i*4);
    *(float4*)(g_efull + (E_ + i)*4) = make_float4(s.x*inv, s.y*inv, s.z*inv, s.w*inv);
}

// ---------------- dual GEMM: xl = h@Wl + bl ; xr = h@Wr + br ----------------
// 64-node x 256-col tile, 8x8 register blocking per thread.
// Both W (128KB) resident in smem; h tile (64x132 padded) in smem, broadcast reads.
#define SHS 132
__global__ __launch_bounds__(256, 1)
void k_gemm(const float* __restrict__ Wl, const float* __restrict__ bl,
            const float* __restrict__ Wr, const float* __restrict__ br, int n){
    extern __shared__ float sm[];
    float* sW = sm;              // [128][256]
    float* sh = sm + DD*256;     // [64][SHS]
    int t = threadIdx.x, cg = t & 31, ng = t >> 5;

    for (int idx = t; idx < DD*DD; idx += 256){
        int k = idx >> 7, c = idx & 127;
        sW[k*256 + c]       = Wl[idx];
        sW[k*256 + 128 + c] = Wr[idx];
    }
    float bias[8];
#pragma unroll
    for (int j = 0; j < 8; ++j){
        int c = cg*8 + j;
        bias[j] = (c < DD) ? bl[c] : br[c - DD];
    }

    int tiles = (n + 63) >> 6;
    float4 pre[8];

    // prefetch first tile: per warp, node = r*8 + (fixed per warp), lane covers k
    {
        int base = blockIdx.x * 64;
#pragma unroll
        for (int r = 0; r < 8; ++r){
            int i = r*256 + t;
            int node = i >> 5, k4 = (i & 31)*4;
            int gn = base + node;
            pre[r] = (gn < n) ? *(const float4*)(g_h + (long long)gn*DD + k4)
                              : make_float4(0.f,0.f,0.f,0.f);
        }
    }

    for (int tile = blockIdx.x; tile < tiles; tile += GDIM){
        __syncthreads();
#pragma unroll
        for (int r = 0; r < 8; ++r){
            int i = r*256 + t;
            int node = i >> 5, k4 = (i & 31)*4;
            *(float4*)(sh + node*SHS + k4) = pre[r];
        }
        __syncthreads();
        if (tile + GDIM < tiles){
            int base = (tile + GDIM) * 64;
#pragma unroll
            for (int r = 0; r < 8; ++r){
                int i = r*256 + t;
                int node = i >> 5, k4 = (i & 31)*4;
                int gn = base + node;
                pre[r] = (gn < n) ? *(const float4*)(g_h + (long long)gn*DD + k4)
                                  : make_float4(0.f,0.f,0.f,0.f);
            }
        }

        float acc[8][8];
#pragma unroll
        for (int i = 0; i < 8; ++i)
#pragma unroll
            for (int j = 0; j < 8; ++j) acc[i][j] = bias[j];

#pragma unroll 1
        for (int k = 0; k < DD; k += 4){
            float hvf[32];
#pragma unroll
            for (int i = 0; i < 8; ++i){
                float4 hv = *(const float4*)(sh + (ng*8 + i)*SHS + k);
                hvf[i*4+0] = hv.x; hvf[i*4+1] = hv.y; hvf[i*4+2] = hv.z; hvf[i*4+3] = hv.w;
            }
#pragma unroll
            for (int kk = 0; kk < 4; ++kk){
                const float* wrow = sW + (k + kk)*256 + cg*8;
                float4 w0 = *(const float4*)(wrow);
                float4 w1 = *(const float4*)(wrow + 4);
                float wv[8] = {w0.x,w0.y,w0.z,w0.w,w1.x,w1.y,w1.z,w1.w};
#pragma unroll
                for (int i = 0; i < 8; ++i){
                    float hval = hvf[i*4 + kk];
#pragma unroll
                    for (int j = 0; j < 8; ++j)
                        acc[i][j] += hval * wv[j];
                }
            }
        }

        int base = tile*64;
        float* outp = (cg < 16) ? g_xl : g_xr;
        int ccol = (cg < 16) ? cg*8 : (cg - 16)*8;
#pragma unroll
        for (int i = 0; i < 8; ++i){
            int gn = base + ng*8 + i;
            if (gn < n){
                *(float4*)(outp + (long long)gn*DD + ccol)
                    = make_float4(acc[i][0], acc[i][1], acc[i][2], acc[i][3]);
                *(float4*)(outp + (long long)gn*DD + ccol + 4)
                    = make_float4(acc[i][4], acc[i][5], acc[i][6], acc[i][7]);
            }
        }
    }
}

// ---------------- fused edge pass: logit -> w=exp(logit) -> z atomics + numerator ----------------
// One warp per (edge or self-loop). Logits are small (inputs scaled 0.05), so
// unnormalized exp is exact-equivalent to max-subtracted softmax.
__global__ void k_att(const int* __restrict__ ei, const float* __restrict__ We,
                      const float* __restrict__ att, int E_, int n, int zbuf){
    __shared__ float sWe[4*DD];
    __shared__ float sAtt[DD];
    int t = threadIdx.x;
    for (int i = t; i < 4*DD; i += 256) sWe[i] = We[i];
    if (t < DD) sAtt[t] = att[t];
    __syncthreads();

    int gw   = blockIdx.x*8 + (t >> 5);
    int lane = t & 31;
    int M = E_ + n;
    if (gw >= M) return;
    int src, dst;
    if (gw < E_){ src = ei[gw]; dst = ei[E_ + gw]; } else { src = dst = gw - E_; }

    int c0 = lane*4;
    float4 a4 = *(const float4*)(g_xl + (long long)src*DD + c0);
    float4 b4 = *(const float4*)(g_xr + (long long)dst*DD + c0);
    float4 e4 = *(const float4*)(g_efull + (long long)gw*4);
    float av[4] = {a4.x, a4.y, a4.z, a4.w};
    float bv[4] = {b4.x, b4.y, b4.z, b4.w};
    float p = 0.f;
#pragma unroll
    for (int j = 0; j < 4; ++j){
        int c = c0 + j;
        float ee = e4.x*sWe[c] + e4.y*sWe[DD + c] + e4.z*sWe[2*DD + c] + e4.w*sWe[3*DD + c];
        float g = av[j] + bv[j] + ee;
        g = (g > 0.f) ? g : 0.2f*g;
        p += g * sAtt[c];
    }
    p += __shfl_xor_sync(0xffffffffu, p, 1);
    p += __shfl_xor_sync(0xffffffffu, p, 2);
    p += __shfl_xor_sync(0xffffffffu, p, 4);

    float w = 0.f;
    if ((lane & 7) == 0){
        int h = lane >> 3;
        w = expf(p);
        atomicAdd(&g_z[zbuf][dst*4 + h], w);
    }
    w = __shfl_sync(0xffffffffu, w, lane & 24);  // broadcast from head leader
    red4(g_num + (long long)dst*DD + c0, av[0]*w, av[1]*w, av[2]*w, av[3]*w);
}

// ---------------- finalize: h = num/(z+1e-16) + cb ; relu ; re-zero scratch ----------------
__global__ void k_fin(const float* __restrict__ cb, int n, int dorelu, int zbuf){
    int idx = blockIdx.x*blockDim.x + threadIdx.x;
    if (idx >= n*DD) return;
    int i = idx >> 7, c = idx & 127;
    float v = g_num[idx] / (g_z[zbuf][(i << 2) + (c >> 5)] + 1e-16f) + cb[c];
    if (dorelu) v = fmaxf(v, 0.0f);
    g_h[idx] = v;
    g_num[idx] = 0.f;                     // ready for next layer
    if (idx < n*4) g_z[zbuf ^ 1][idx] = 0.f;  // next layer's z buffer (prev reads done)
}

// ---------------- head ----------------
__global__ void k_head(float* out, const float* __restrict__ bout, int G){
    int g = blockIdx.x*blockDim.x + threadIdx.x;
    if (g < G) out[g] = bout[0];
}

__global__ void k_pool(const float* __restrict__ Wout, const int* __restrict__ bid,
                       float* out, int n){
    int gw   = blockIdx.x*8 + (threadIdx.x >> 5);
    int lane = threadIdx.x & 31;
    if (gw >= n) return;
    float4 hv = *(const float4*)(g_h + (long long)gw*DD + lane*4);
    float4 wv = *(const float4*)(Wout + lane*4);
    float p = hv.x*wv.x + hv.y*wv.y + hv.z*wv.z + hv.w*wv.w;
#pragma unroll
    for (int o = 16; o > 0; o >>= 1) p += __shfl_xor_sync(0xffffffffu, p, o);
    if (lane == 0) atomicAdd(out + bid[gw], p);
}

// ---------------- launch ----------------
extern "C" void kernel_launch(void* const* d_in, const int* in_sizes, int n_in,
                              void* d_out, int out_size){
    const float* atab = (const float*)d_in[0];
    const float* bond = (const float*)d_in[1];
    const float* Wl   = (const float*)d_in[2];
    const float* bl   = (const float*)d_in[3];
    const float* Wr   = (const float*)d_in[4];
    const float* br   = (const float*)d_in[5];
    const float* We   = (const float*)d_in[6];
    const float* att  = (const float*)d_in[7];
    const float* cb   = (const float*)d_in[8];
    const float* Wout = (const float*)d_in[9];
    const float* bout = (const float*)d_in[10];
    const int*   x    = (const int*)d_in[11];
    const int*   ei   = (const int*)d_in[12];
    const int*   ea   = (const int*)d_in[13];
    const int*   bid  = (const int*)d_in[14];

    int n  = in_sizes[11] / 9;
    int E_ = in_sizes[13];
    int G  = out_size;
    float* out = (float*)d_out;

    const int SMEM = DD*256*4 + 64*SHS*4;  // 128KB + 33KB
    static int cfg_done = 0;
    if (!cfg_done){
        cudaFuncSetAttribute(k_gemm, cudaFuncAttributeMaxDynamicSharedMemorySize, SMEM);
        cfg_done = 1;
    }

    int nb = (n + 255)/256;
    int M  = E_ + n;
    int mb = (M + 7)/8;

    k_atom<<<n, 128>>>(atab, x, n);
    k_init<<<1024, 256>>>(n);
    k_edge<<<(E_ + 255)/256, 256>>>(bond, ei, ea, E_);
    k_self<<<nb, 256>>>(E_, n);

    for (int l = 0; l < 4; ++l){
        int zbuf = l & 1;
        k_gemm<<<GDIM, 256, SMEM>>>(Wl + l*DD*DD, bl + l*DD, Wr + l*DD*DD, br + l*DD, n);
        k_att<<<mb, 256>>>(ei, We + l*4*DD, att + l*DD, E_, n, zbuf);
        k_fin<<<(n*DD + 255)/256, 256>>>(cb + l*DD, n, (l < 3) ? 1 : 0, zbuf);
    }

    k_head<<<(G + 255)/256, 256>>>(out, bout, G);
    k_pool<<<(n + 7)/8, 256>>>(Wout, bid, out, n);
}

// round 4
// speedup vs baseline: 3.2294x; 1.5336x over previous
#include <cuda_runtime.h>
#include <cstdint>

#define NMAX 200000
#define EMAX 400000
#define DD 128
#define HH 4
#define GDIM 148

// ---------------- scratch (device globals; no allocation) ----------------
__device__ __align__(16) float g_h[NMAX*DD];
__device__ __align__(16) float g_xl[NMAX*DD];
__device__ __align__(16) float g_xr[NMAX*DD];
__device__ __align__(16) float g_num[NMAX*DD];
__device__ __align__(16) float g_efull[(EMAX+NMAX)*HH];
__device__ __align__(16) float g_sums[NMAX*HH];
__device__ float g_z[2][NMAX*HH];       // double-buffered softmax denominators
__device__ float g_cnt[NMAX];

// vector float4 reduction (sm_90+)
__device__ __forceinline__ void red4(float* p, float a, float b, float c, float d){
    asm volatile("red.global.add.v4.f32 [%0], {%1,%2,%3,%4};"
                 :: "l"(p), "f"(a), "f"(b), "f"(c), "f"(d) : "memory");
}

__device__ __forceinline__ uint32_t cvt_tf32(float f){
    uint32_t r; asm("cvt.rna.tf32.f32 %0, %1;" : "=r"(r) : "f"(f)); return r;
}

// ---------------- atom encoder ----------------
__global__ void k_atom(const float* __restrict__ tab, const int* __restrict__ x, int n){
    int i = blockIdx.x;
    int d = threadIdx.x;
    __shared__ int xf[9];
    if (d < 9) xf[d] = x[i*9 + d];
    __syncthreads();
    float s = 0.f;
#pragma unroll
    for (int f = 0; f < 9; ++f)
        s += tab[(f*16 + xf[f])*DD + d];
    g_h[i*DD + d] = s;
}

__global__ void k_init(int n){
    long long idx = (long long)blockIdx.x*blockDim.x + threadIdx.x;
    long long tot = (long long)n*DD;
    for (long long i = idx; i < tot; i += (long long)gridDim.x*blockDim.x)
        g_num[i] = 0.f;
    if (idx < n){
        g_cnt[idx] = 0.f;
        *(float4*)(g_sums + idx*4) = make_float4(0.f,0.f,0.f,0.f);
        *(float4*)(&g_z[0][idx*4]) = make_float4(0.f,0.f,0.f,0.f);
        *(float4*)(&g_z[1][idx*4]) = make_float4(0.f,0.f,0.f,0.f);
    }
}

__global__ void k_edge(const float* __restrict__ bond, const int* __restrict__ ei,
                       const int* __restrict__ ea, int E_){
    int e = blockIdx.x*blockDim.x + threadIdx.x;
    if (e >= E_) return;
    int tt  = ea[e];
    int dst = ei[E_ + e];
    float4 b = *(const float4*)(bond + tt*4);
    *(float4*)(g_efull + e*4) = b;
    red4(g_sums + dst*4, b.x, b.y, b.z, b.w);
    atomicAdd(g_cnt + dst, 1.0f);
}

__global__ void k_self(int E_, int n){
    int i = blockIdx.x*blockDim.x + threadIdx.x;
    if (i >= n) return;
    float inv = 1.0f / fmaxf(g_cnt[i], 1.0f);
    float4 s = *(const float4*)(g_sums + i*4);
    *(float4*)(g_efull + (E_ + i)*4) = make_float4(s.x*inv, s.y*inv, s.z*inv, s.w*inv);
}

// ---------------- tf32 mma.sync dual GEMM: [xl|xr] = h @ [Wl|Wr] + bias ----------------
// B = [Wl^T ; Wr^T] tf32 in smem [256][132] (built once per persistent CTA).
// CTA tile M=64, N=256: 8 warps = 2(M) x 4(N), warp tile 32x64.
// mma.sync.aligned.m16n8k8.row.col.f32.tf32.tf32.f32
#define SBS 132
__global__ __launch_bounds__(256, 1)
void k_tc(const float* __restrict__ Wl, const float* __restrict__ bl,
          const float* __restrict__ Wr, const float* __restrict__ br, int n){
    extern __shared__ float sm[];
    float* sB    = sm;               // [256][SBS] tf32 bits
    float* sA    = sm + 256*SBS;     // [64][SBS] tf32 bits
    float* sBias = sA + 64*SBS;      // [256]
    int tid = threadIdx.x, wid = tid >> 5, lane = tid & 31;
    int gq = lane >> 2, tg = lane & 3;      // groupID, threadID-in-group
    int wm = wid & 1, wn = wid >> 1;        // warp tile: rows wm*32, cols wn*64

    // build B = [Wl^T ; Wr^T] (coalesced gmem over c)
    for (int idx = tid; idx < 128*256; idx += 256){
        int k = idx >> 8, c = idx & 255;
        float w = (c < 128) ? Wl[k*DD + c] : Wr[k*DD + (c - 128)];
        sB[c*SBS + k] = __uint_as_float(cvt_tf32(w));
    }
    sBias[tid] = (tid < 128) ? bl[tid] : br[tid - 128];

    int tiles = (n + 63) >> 6;
    float4 pre[8];
    {
        int base = blockIdx.x * 64;
#pragma unroll
        for (int r = 0; r < 8; ++r){
            int i = r*256 + tid;
            int node = i >> 5, k4 = (i & 31)*4;
            int gn = base + node;
            pre[r] = (gn < n) ? *(const float4*)(g_h + (size_t)gn*DD + k4)
                              : make_float4(0.f,0.f,0.f,0.f);
        }
    }

    for (int tile = blockIdx.x; tile < tiles; tile += GDIM){
        __syncthreads();
#pragma unroll
        for (int r = 0; r < 8; ++r){
            int i = r*256 + tid;
            int node = i >> 5, k4 = (i & 31)*4;
            uint32_t* p = (uint32_t*)(sA + node*SBS + k4);
            p[0] = cvt_tf32(pre[r].x); p[1] = cvt_tf32(pre[r].y);
            p[2] = cvt_tf32(pre[r].z); p[3] = cvt_tf32(pre[r].w);
        }
        __syncthreads();
        if (tile + GDIM < tiles){
            int base = (tile + GDIM) * 64;
#pragma unroll
            for (int r = 0; r < 8; ++r){
                int i = r*256 + tid;
                int node = i >> 5, k4 = (i & 31)*4;
                int gn = base + node;
                pre[r] = (gn < n) ? *(const float4*)(g_h + (size_t)gn*DD + k4)
                                  : make_float4(0.f,0.f,0.f,0.f);
            }
        }

        float acc[2][8][4];
#pragma unroll
        for (int mb = 0; mb < 2; ++mb)
#pragma unroll
            for (int nb = 0; nb < 8; ++nb)
#pragma unroll
                for (int j = 0; j < 4; ++j) acc[mb][nb][j] = 0.f;

#pragma unroll 4
        for (int kc = 0; kc < 16; ++kc){
            int k = kc*8;
            uint32_t a[2][4];
#pragma unroll
            for (int mb = 0; mb < 2; ++mb){
                int r0 = wm*32 + mb*16 + gq;
                const uint32_t* pa0 = (const uint32_t*)(sA + r0*SBS + k + tg);
                const uint32_t* pa1 = (const uint32_t*)(sA + (r0+8)*SBS + k + tg);
                a[mb][0] = pa0[0];
                a[mb][1] = pa1[0];
                a[mb][2] = pa0[4];
                a[mb][3] = pa1[4];
            }
#pragma unroll
            for (int nb = 0; nb < 8; ++nb){
                int nn = wn*64 + nb*8 + gq;
                const uint32_t* pb = (const uint32_t*)(sB + nn*SBS + k + tg);
                uint32_t b0 = pb[0], b1 = pb[4];
#pragma unroll
                for (int mb = 0; mb < 2; ++mb){
                    asm volatile(
                        "mma.sync.aligned.m16n8k8.row.col.f32.tf32.tf32.f32 "
                        "{%0,%1,%2,%3}, {%4,%5,%6,%7}, {%8,%9}, {%0,%1,%2,%3};"
                        : "+f"(acc[mb][nb][0]), "+f"(acc[mb][nb][1]),
                          "+f"(acc[mb][nb][2]), "+f"(acc[mb][nb][3])
                        : "r"(a[mb][0]), "r"(a[mb][1]), "r"(a[mb][2]), "r"(a[mb][3]),
                          "r"(b0), "r"(b1));
                }
            }
        }

        int base = tile*64;
#pragma unroll
        for (int mb = 0; mb < 2; ++mb){
            int gm0 = base + wm*32 + mb*16 + gq;
            int gm1 = gm0 + 8;
#pragma unroll
            for (int nb = 0; nb < 8; ++nb){
                int c0 = wn*64 + nb*8 + tg*2;
                float bx = sBias[c0], by = sBias[c0 + 1];
                float* outp = (c0 < 128) ? g_xl : g_xr;
                int cl = (c0 < 128) ? c0 : c0 - 128;
                if (gm0 < n)
                    *(float2*)(outp + (size_t)gm0*DD + cl)
                        = make_float2(acc[mb][nb][0] + bx, acc[mb][nb][1] + by);
                if (gm1 < n)
                    *(float2*)(outp + (size_t)gm1*DD + cl)
                        = make_float2(acc[mb][nb][2] + bx, acc[mb][nb][3] + by);
            }
        }
    }
}

// ---------------- fused edge pass ----------------
__global__ void k_att(const int* __restrict__ ei, const float* __restrict__ We,
                      const float* __restrict__ att, int E_, int n, int zbuf){
    __shared__ float sWe[4*DD];
    __shared__ float sAtt[DD];
    int t = threadIdx.x;
    for (int i = t; i < 4*DD; i += 256) sWe[i] = We[i];
    if (t < DD) sAtt[t] = att[t];
    __syncthreads();

    int gw   = blockIdx.x*8 + (t >> 5);
    int lane = t & 31;
    int M = E_ + n;
    if (gw >= M) return;
    int src, dst;
    if (gw < E_){ src = ei[gw]; dst = ei[E_ + gw]; } else { src = dst = gw - E_; }

    int c0 = lane*4;
    float4 a4 = *(const float4*)(g_xl + (size_t)src*DD + c0);
    float4 b4 = *(const float4*)(g_xr + (size_t)dst*DD + c0);
    float4 e4 = *(const float4*)(g_efull + (size_t)gw*4);
    float av[4] = {a4.x, a4.y, a4.z, a4.w};
    float bv[4] = {b4.x, b4.y, b4.z, b4.w};
    float p = 0.f;
#pragma unroll
    for (int j = 0; j < 4; ++j){
        int c = c0 + j;
        float ee = e4.x*sWe[c] + e4.y*sWe[DD + c] + e4.z*sWe[2*DD + c] + e4.w*sWe[3*DD + c];
        float g = av[j] + bv[j] + ee;
        g = (g > 0.f) ? g : 0.2f*g;
        p += g * sAtt[c];
    }
    p += __shfl_xor_sync(0xffffffffu, p, 1);
    p += __shfl_xor_sync(0xffffffffu, p, 2);
    p += __shfl_xor_sync(0xffffffffu, p, 4);

    float w = 0.f;
    if ((lane & 7) == 0){
        int h = lane >> 3;
        w = expf(p);
        atomicAdd(&g_z[zbuf][dst*4 + h], w);
    }
    w = __shfl_sync(0xffffffffu, w, lane & 24);
    red4(g_num + (size_t)dst*DD + c0, av[0]*w, av[1]*w, av[2]*w, av[3]*w);
}

// ---------------- finalize ----------------
__global__ void k_fin(const float* __restrict__ cb, int n, int dorelu, int zbuf){
    int idx = blockIdx.x*blockDim.x + threadIdx.x;
    if (idx >= n*DD) return;
    int i = idx >> 7, c = idx & 127;
    float v = g_num[idx] / (g_z[zbuf][(i << 2) + (c >> 5)] + 1e-16f) + cb[c];
    if (dorelu) v = fmaxf(v, 0.0f);
    g_h[idx] = v;
    g_num[idx] = 0.f;
    if (idx < n*4) g_z[zbuf ^ 1][idx] = 0.f;
}

// ---------------- head ----------------
__global__ void k_head(float* out, const float* __restrict__ bout, int G){
    int g = blockIdx.x*blockDim.x + threadIdx.x;
    if (g < G) out[g] = bout[0];
}

__global__ void k_pool(const float* __restrict__ Wout, const int* __restrict__ bid,
                       float* out, int n){
    int gw   = blockIdx.x*8 + (threadIdx.x >> 5);
    int lane = threadIdx.x & 31;
    if (gw >= n) return;
    float4 hv = *(const float4*)(g_h + (size_t)gw*DD + lane*4);
    float4 wv = *(const float4*)(Wout + lane*4);
    float p = hv.x*wv.x + hv.y*wv.y + hv.z*wv.z + hv.w*wv.w;
#pragma unroll
    for (int o = 16; o > 0; o >>= 1) p += __shfl_xor_sync(0xffffffffu, p, o);
    if (lane == 0) atomicAdd(out + bid[gw], p);
}

// ---------------- launch ----------------
extern "C" void kernel_launch(void* const* d_in, const int* in_sizes, int n_in,
                              void* d_out, int out_size){
    const float* atab = (const float*)d_in[0];
    const float* bond = (const float*)d_in[1];
    const float* Wl   = (const float*)d_in[2];
    const float* bl   = (const float*)d_in[3];
    const float* Wr   = (const float*)d_in[4];
    const float* br   = (const float*)d_in[5];
    const float* We   = (const float*)d_in[6];
    const float* att  = (const float*)d_in[7];
    const float* cb   = (const float*)d_in[8];
    const float* Wout = (const float*)d_in[9];
    const float* bout = (const float*)d_in[10];
    const int*   x    = (const int*)d_in[11];
    const int*   ei   = (const int*)d_in[12];
    const int*   ea   = (const int*)d_in[13];
    const int*   bid  = (const int*)d_in[14];

    int n  = in_sizes[11] / 9;
    int E_ = in_sizes[13];
    int G  = out_size;
    float* out = (float*)d_out;

    const int SMEM = (256*SBS + 64*SBS + 256) * 4;   // ~166 KB
    cudaFuncSetAttribute(k_tc, cudaFuncAttributeMaxDynamicSharedMemorySize, SMEM);

    int nb = (n + 255)/256;
    int M  = E_ + n;
    int mb = (M + 7)/8;

    k_atom<<<n, 128>>>(atab, x, n);
    k_init<<<1024, 256>>>(n);
    k_edge<<<(E_ + 255)/256, 256>>>(bond, ei, ea, E_);
    k_self<<<nb, 256>>>(E_, n);

    for (int l = 0; l < 4; ++l){
        int zbuf = l & 1;
        k_tc<<<GDIM, 256, SMEM>>>(Wl + l*DD*DD, bl + l*DD, Wr + l*DD*DD, br + l*DD, n);
        k_att<<<mb, 256>>>(ei, We + l*4*DD, att + l*DD, E_, n, zbuf);
        k_fin<<<(n*DD + 255)/256, 256>>>(cb + l*DD, n, (l < 3) ? 1 : 0, zbuf);
    }

    k_head<<<(G + 255)/256, 256>>>(out, bout, G);
    k_pool<<<(n + 7)/8, 256>>>(Wout, bid, out, n);
}

// round 5
// speedup vs baseline: 3.3078x; 1.0243x over previous
#include <cuda_runtime.h>
#include <cuda_bf16.h>
#include <cstdint>

#define NMAX 200000
#define EMAX 400000
#define DD 128
#define HH 4
#define GDIM 148

// ---------------- scratch (device globals; no allocation) ----------------
__device__ __align__(16) float g_h[NMAX*DD];
__device__ __align__(16) float g_xl[NMAX*DD];
__device__ __align__(16) float g_xr[NMAX*DD];
__device__ __align__(16) float g_efull[(EMAX+NMAX)*HH];
__device__ __align__(16) float g_sums[NMAX*HH];
__device__ int g_deg[NMAX];
__device__ int g_off[NMAX+1];
__device__ int g_cur[NMAX];
__device__ int g_eid[EMAX+NMAX];
__device__ int g_bsum[260];

// vector float4 reduction (sm_90+)
__device__ __forceinline__ void red4(float* p, float a, float b, float c, float d){
    asm volatile("red.global.add.v4.f32 [%0], {%1,%2,%3,%4};"
                 :: "l"(p), "f"(a), "f"(b), "f"(c), "f"(d) : "memory");
}

// split a pair of floats into bf16x2 (hi) + bf16x2 (lo residual)
__device__ __forceinline__ uint2 split2(float x0, float x1){
    __nv_bfloat162 h = __floats2bfloat162_rn(x0, x1);
    float r0 = x0 - __bfloat162float(h.x);
    float r1 = x1 - __bfloat162float(h.y);
    __nv_bfloat162 l = __floats2bfloat162_rn(r0, r1);
    uint2 u;
    u.x = *reinterpret_cast<uint32_t*>(&h);
    u.y = *reinterpret_cast<uint32_t*>(&l);
    return u;
}

// ---------------- atom encoder ----------------
__global__ void k_atom(const float* __restrict__ tab, const int* __restrict__ x, int n){
    int i = blockIdx.x;
    int d = threadIdx.x;
    __shared__ int xf[9];
    if (d < 9) xf[d] = x[i*9 + d];
    __syncthreads();
    float s = 0.f;
#pragma unroll
    for (int f = 0; f < 9; ++f)
        s += tab[(f*16 + xf[f])*DD + d];
    g_h[i*DD + d] = s;
}

__global__ void k_zero(int n){
    int i = blockIdx.x*blockDim.x + threadIdx.x;
    if (i >= n) return;
    g_deg[i] = 0;
    *(float4*)(g_sums + i*4) = make_float4(0.f,0.f,0.f,0.f);
}

// bond embeddings + per-dst degree + sums for self-loop mean
__global__ void k_edge(const float* __restrict__ bond, const int* __restrict__ ei,
                       const int* __restrict__ ea, int E_){
    int e = blockIdx.x*blockDim.x + threadIdx.x;
    if (e >= E_) return;
    int tt  = ea[e];
    int dst = ei[E_ + e];
    float4 b = *(const float4*)(bond + tt*4);
    *(float4*)(g_efull + e*4) = b;
    red4(g_sums + dst*4, b.x, b.y, b.z, b.w);
    atomicAdd(g_deg + dst, 1);
}

__global__ void k_self(int E_, int n){
    int i = blockIdx.x*blockDim.x + threadIdx.x;
    if (i >= n) return;
    float inv = 1.0f / fmaxf((float)g_deg[i], 1.0f);
    float4 s = *(const float4*)(g_sums + i*4);
    *(float4*)(g_efull + (E_ + i)*4) = make_float4(s.x*inv, s.y*inv, s.z*inv, s.w*inv);
}

// ---------------- CSR build: off = exscan(deg+1); eid scatter ----------------
__global__ void k_scan1(int n){
    __shared__ int ws[8];
    int t = threadIdx.x, b = blockIdx.x;
    int base = b*1024 + t*4;
    int v[4];
#pragma unroll
    for (int j = 0; j < 4; ++j){
        int i = base + j;
        v[j] = (i < n) ? (g_deg[i] + 1) : 0;
    }
    int s = v[0] + v[1] + v[2] + v[3];
    int lane = t & 31, wid = t >> 5;
    int x = s;
#pragma unroll
    for (int o = 1; o < 32; o <<= 1){
        int y = __shfl_up_sync(0xffffffffu, x, o);
        if (lane >= o) x += y;
    }
    if (lane == 31) ws[wid] = x;
    __syncthreads();
    if (t == 0){
        int r = 0;
#pragma unroll
        for (int w = 0; w < 8; ++w){ int tmp = ws[w]; ws[w] = r; r += tmp; }
        g_bsum[b] = r;
    }
    __syncthreads();
    int run = x - s + ws[wid];
#pragma unroll
    for (int j = 0; j < 4; ++j){
        int i = base + j;
        if (i < n) g_off[i] = run;
        run += v[j];
    }
}

__global__ void k_scan2(int nb){
    int r = 0;
    for (int b = 0; b < nb; ++b){ int t = g_bsum[b]; g_bsum[b] = r; r += t; }
    g_bsum[nb] = r;
}

__global__ void k_scan3(int n, int nb){
    int i = blockIdx.x*blockDim.x + threadIdx.x;
    if (i == 0) g_off[n] = g_bsum[nb];
    if (i >= n) return;
    int o = g_off[i] + g_bsum[i >> 10];
    g_off[i] = o;
    g_cur[i] = o;
}

__global__ void k_scatter(const int* __restrict__ ei, int E_, int n){
    int e = blockIdx.x*blockDim.x + threadIdx.x;
    if (e >= E_ + n) return;
    int dst = (e < E_) ? ei[E_ + e] : (e - E_);
    int pos = atomicAdd(g_cur + dst, 1);
    g_eid[pos] = e;
}

// ---------------- bf16-split dual GEMM: [xl|xr] = h @ [Wl|Wr] + bias ----------------
// Each fp32 operand split hi+lo bf16; 3 MMA terms (hh, hl, lh) per tile -> ~fp32 accuracy.
// B = [Wl^T ; Wr^T] in smem [256 cols][64 kpairs] of uint2{hi2,lo2}; A tile [64][64] uint2.
// mma.sync.aligned.m16n8k16.row.col.f32.bf16.bf16.f32, CTA tile 64x256, 8 warps 2x4.
#define SAST 66   // uint2 row stride (stride%16 == 2 -> conflict-free frag loads)
#define MMA3(acc, ah, al, bh0, bh1, bl0, bl1) do { \
    asm volatile("mma.sync.aligned.m16n8k16.row.col.f32.bf16.bf16.f32 " \
        "{%0,%1,%2,%3}, {%4,%5,%6,%7}, {%8,%9}, {%0,%1,%2,%3};" \
        : "+f"(acc[0]), "+f"(acc[1]), "+f"(acc[2]), "+f"(acc[3]) \
        : "r"(ah[0]), "r"(ah[1]), "r"(ah[2]), "r"(ah[3]), "r"(bh0), "r"(bh1)); \
    asm volatile("mma.sync.aligned.m16n8k16.row.col.f32.bf16.bf16.f32 " \
        "{%0,%1,%2,%3}, {%4,%5,%6,%7}, {%8,%9}, {%0,%1,%2,%3};" \
        : "+f"(acc[0]), "+f"(acc[1]), "+f"(acc[2]), "+f"(acc[3]) \
        : "r"(ah[0]), "r"(ah[1]), "r"(ah[2]), "r"(ah[3]), "r"(bl0), "r"(bl1)); \
    asm volatile("mma.sync.aligned.m16n8k16.row.col.f32.bf16.bf16.f32 " \
        "{%0,%1,%2,%3}, {%4,%5,%6,%7}, {%8,%9}, {%0,%1,%2,%3};" \
        : "+f"(acc[0]), "+f"(acc[1]), "+f"(acc[2]), "+f"(acc[3]) \
        : "r"(al[0]), "r"(al[1]), "r"(al[2]), "r"(al[3]), "r"(bh0), "r"(bh1)); \
} while(0)

__global__ __launch_bounds__(256, 1)
void k_tc(const float* __restrict__ Wl, const float* __restrict__ bl,
          const float* __restrict__ Wr, const float* __restrict__ br, int n){
    extern __shared__ uint2 smu[];
    uint2* sB = smu;                   // [256][SAST]
    uint2* sA = smu + 256*SAST;        // [64][SAST]
    float* sBias = (float*)(smu + 256*SAST + 64*SAST);  // [256]
    int tid = threadIdx.x, wid = tid >> 5, lane = tid & 31;
    int gq = lane >> 2, tg = lane & 3;
    int wm = wid & 1, wn = wid >> 1;

    // build B (coalesced over c)
    for (int idx = tid; idx < 256*64; idx += 256){
        int c = idx & 255, kp = idx >> 8;
        int k = kp*2;
        float w0, w1;
        if (c < 128){ w0 = Wl[k*DD + c];        w1 = Wl[(k+1)*DD + c]; }
        else        { w0 = Wr[k*DD + (c-128)];  w1 = Wr[(k+1)*DD + (c-128)]; }
        sB[c*SAST + kp] = split2(w0, w1);
    }
    sBias[tid] = (tid < 128) ? bl[tid] : br[tid - 128];

    int tiles = (n + 63) >> 6;
    float4 pre[8];
    {
        int base = blockIdx.x * 64;
#pragma unroll
        for (int r = 0; r < 8; ++r){
            int i = r*256 + tid;
            int node = i >> 5, k4 = (i & 31)*4;
            int gn = base + node;
            pre[r] = (gn < n) ? *(const float4*)(g_h + (size_t)gn*DD + k4)
                              : make_float4(0.f,0.f,0.f,0.f);
        }
    }

    for (int tile = blockIdx.x; tile < tiles; tile += GDIM){
        __syncthreads();
#pragma unroll
        for (int r = 0; r < 8; ++r){
            int i = r*256 + tid;
            int node = i >> 5, k4 = (i & 31)*4;
            sA[node*SAST + (k4 >> 1)]     = split2(pre[r].x, pre[r].y);
            sA[node*SAST + (k4 >> 1) + 1] = split2(pre[r].z, pre[r].w);
        }
        __syncthreads();
        if (tile + GDIM < tiles){
            int base = (tile + GDIM) * 64;
#pragma unroll
            for (int r = 0; r < 8; ++r){
                int i = r*256 + tid;
                int node = i >> 5, k4 = (i & 31)*4;
                int gn = base + node;
                pre[r] = (gn < n) ? *(const float4*)(g_h + (size_t)gn*DD + k4)
                                  : make_float4(0.f,0.f,0.f,0.f);
            }
        }

        float acc[2][8][4];
#pragma unroll
        for (int mb = 0; mb < 2; ++mb)
#pragma unroll
            for (int nb = 0; nb < 8; ++nb)
#pragma unroll
                for (int j = 0; j < 4; ++j) acc[mb][nb][j] = 0.f;

#pragma unroll 2
        for (int kc = 0; kc < 8; ++kc){
            int kp0 = kc*8 + tg;
            uint32_t ah[2][4], al[2][4];
#pragma unroll
            for (int mb = 0; mb < 2; ++mb){
                int r0 = wm*32 + mb*16 + gq;
                uint2 p0 = sA[r0*SAST + kp0];
                uint2 p1 = sA[(r0+8)*SAST + kp0];
                uint2 p2 = sA[r0*SAST + kp0 + 4];
                uint2 p3 = sA[(r0+8)*SAST + kp0 + 4];
                ah[mb][0] = p0.x; ah[mb][1] = p1.x; ah[mb][2] = p2.x; ah[mb][3] = p3.x;
                al[mb][0] = p0.y; al[mb][1] = p1.y; al[mb][2] = p2.y; al[mb][3] = p3.y;
            }
#pragma unroll
            for (int nb = 0; nb < 8; ++nb){
                int col = wn*64 + nb*8 + gq;
                uint2 pb0 = sB[col*SAST + kp0];
                uint2 pb1 = sB[col*SAST + kp0 + 4];
#pragma unroll
                for (int mb = 0; mb < 2; ++mb)
                    MMA3(acc[mb][nb], ah[mb], al[mb], pb0.x, pb1.x, pb0.y, pb1.y);
            }
        }

        int base = tile*64;
#pragma unroll
        for (int mb = 0; mb < 2; ++mb){
            int gm0 = base + wm*32 + mb*16 + gq;
            int gm1 = gm0 + 8;
#pragma unroll
            for (int nb = 0; nb < 8; ++nb){
                int c0 = wn*64 + nb*8 + tg*2;
                float bx = sBias[c0], by = sBias[c0 + 1];
                float* outp = (c0 < 128) ? g_xl : g_xr;
                int cl = (c0 < 128) ? c0 : c0 - 128;
                if (gm0 < n)
                    *(float2*)(outp + (size_t)gm0*DD + cl)
                        = make_float2(acc[mb][nb][0] + bx, acc[mb][nb][1] + by);
                if (gm1 < n)
                    *(float2*)(outp + (size_t)gm1*DD + cl)
                        = make_float2(acc[mb][nb][2] + bx, acc[mb][nb][3] + by);
            }
        }
    }
}

// ---------------- CSR fused edge pass + normalize + bias + relu -> h ----------------
// One warp per dst node: xr read once, z in registers, write h once. No atomics.
__global__ void k_att2(const int* __restrict__ ei, const float* __restrict__ We,
                       const float* __restrict__ att, const float* __restrict__ cb,
                       int E_, int n, int dorelu){
    __shared__ float sWe[4*DD];
    __shared__ float sAtt[DD];
    __shared__ float sCb[DD];
    int t = threadIdx.x;
    for (int i = t; i < 4*DD; i += 256) sWe[i] = We[i];
    if (t < DD){ sAtt[t] = att[t]; sCb[t] = cb[t]; }
    __syncthreads();

    int d = blockIdx.x*8 + (t >> 5);
    if (d >= n) return;
    int lane = t & 31;
    int off0 = g_off[d], off1 = g_off[d+1];
    int c0 = lane*4;

    float4 b4 = *(const float4*)(g_xr + (size_t)d*DD + c0);
    float acc0 = 0.f, acc1 = 0.f, acc2 = 0.f, acc3 = 0.f;
    float zacc = 0.f;

    for (int jb = off0; jb < off1; jb += 32){
        int m = min(32, off1 - jb);
        int idx = 0, src = d;
        if (lane < m){
            idx = g_eid[jb + lane];
            src = (idx < E_) ? ei[idx] : d;
        }
#pragma unroll 1
        for (int jj = 0; jj < m; ++jj){
            int eidx = __shfl_sync(0xffffffffu, idx, jj);
            int esrc = __shfl_sync(0xffffffffu, src, jj);
            float4 e4 = *(const float4*)(g_efull + (size_t)eidx*4);
            float4 a4 = *(const float4*)(g_xl + (size_t)esrc*DD + c0);
            float av[4] = {a4.x, a4.y, a4.z, a4.w};
            float bv[4] = {b4.x, b4.y, b4.z, b4.w};
            float p = 0.f;
#pragma unroll
            for (int j = 0; j < 4; ++j){
                int c = c0 + j;
                float ee = e4.x*sWe[c] + e4.y*sWe[DD + c]
                         + e4.z*sWe[2*DD + c] + e4.w*sWe[3*DD + c];
                float g = av[j] + bv[j] + ee;
                g = (g > 0.f) ? g : 0.2f*g;
                p += g * sAtt[c];
            }
            p += __shfl_xor_sync(0xffffffffu, p, 1);
            p += __shfl_xor_sync(0xffffffffu, p, 2);
            p += __shfl_xor_sync(0xffffffffu, p, 4);
            float w = 0.f;
            if ((lane & 7) == 0){
                w = expf(p);
                zacc += w;
            }
            w = __shfl_sync(0xffffffffu, w, lane & 24);
            acc0 += av[0]*w; acc1 += av[1]*w; acc2 += av[2]*w; acc3 += av[3]*w;
        }
    }

    float z = __shfl_sync(0xffffffffu, zacc, lane & 24);
    float inv = 1.0f / (z + 1e-16f);
    float4 o;
    o.x = acc0*inv + sCb[c0];
    o.y = acc1*inv + sCb[c0+1];
    o.z = acc2*inv + sCb[c0+2];
    o.w = acc3*inv + sCb[c0+3];
    if (dorelu){
        o.x = fmaxf(o.x, 0.f); o.y = fmaxf(o.y, 0.f);
        o.z = fmaxf(o.z, 0.f); o.w = fmaxf(o.w, 0.f);
    }
    *(float4*)(g_h + (size_t)d*DD + c0) = o;
}

// ---------------- head ----------------
__global__ void k_head(float* out, const float* __restrict__ bout, int G){
    int g = blockIdx.x*blockDim.x + threadIdx.x;
    if (g < G) out[g] = bout[0];
}

__global__ void k_pool(const float* __restrict__ Wout, const int* __restrict__ bid,
                       float* out, int n){
    int gw   = blockIdx.x*8 + (threadIdx.x >> 5);
    int lane = threadIdx.x & 31;
    if (gw >= n) return;
    float4 hv = *(const float4*)(g_h + (size_t)gw*DD + lane*4);
    float4 wv = *(const float4*)(Wout + lane*4);
    float p = hv.x*wv.x + hv.y*wv.y + hv.z*wv.z + hv.w*wv.w;
#pragma unroll
    for (int o = 16; o > 0; o >>= 1) p += __shfl_xor_sync(0xffffffffu, p, o);
    if (lane == 0) atomicAdd(out + bid[gw], p);
}

// ---------------- launch ----------------
extern "C" void kernel_launch(void* const* d_in, const int* in_sizes, int n_in,
                              void* d_out, int out_size){
    const float* atab = (const float*)d_in[0];
    const float* bond = (const float*)d_in[1];
    const float* Wl   = (const float*)d_in[2];
    const float* bl   = (const float*)d_in[3];
    const float* Wr   = (const float*)d_in[4];
    const float* br   = (const float*)d_in[5];
    const float* We   = (const float*)d_in[6];
    const float* att  = (const float*)d_in[7];
    const float* cb   = (const float*)d_in[8];
    const float* Wout = (const float*)d_in[9];
    const float* bout = (const float*)d_in[10];
    const int*   x    = (const int*)d_in[11];
    const int*   ei   = (const int*)d_in[12];
    const int*   ea   = (const int*)d_in[13];
    const int*   bid  = (const int*)d_in[14];

    int n  = in_sizes[11] / 9;
    int E_ = in_sizes[13];
    int G  = out_size;
    float* out = (float*)d_out;

    const int SMEM = (256*SAST + 64*SAST)*8 + 256*4;   // ~170 KB
    cudaFuncSetAttribute(k_tc, cudaFuncAttributeMaxDynamicSharedMemorySize, SMEM);

    int nb = (n + 255)/256;
    int nsb = (n + 1023)/1024;
    int M  = E_ + n;

    k_atom<<<n, 128>>>(atab, x, n);
    k_zero<<<nb, 256>>>(n);
    k_edge<<<(E_ + 255)/256, 256>>>(bond, ei, ea, E_);
    k_self<<<nb, 256>>>(E_, n);

    // CSR build
    k_scan1<<<nsb, 256>>>(n);
    k_scan2<<<1, 1>>>(nsb);
    k_scan3<<<nb, 256>>>(n, nsb);
    k_scatter<<<(M + 255)/256, 256>>>(ei, E_, n);

    for (int l = 0; l < 4; ++l){
        k_tc<<<GDIM, 256, SMEM>>>(Wl + l*DD*DD, bl + l*DD, Wr + l*DD*DD, br + l*DD, n);
        k_att2<<<(n + 7)/8, 256>>>(ei, We + l*4*DD, att + l*DD, cb + l*DD,
                                   E_, n, (l < 3) ? 1 : 0);
    }

    k_head<<<(G + 255)/256, 256>>>(out, bout, G);
    k_pool<<<(n + 7)/8, 256>>>(Wout, bid, out, n);
}